// round 9
// baseline (speedup 1.0000x reference)
#include <cuda_runtime.h>
#include <cuda_fp16.h>
#include <stdint.h>

// Problem constants
#define B_ 16384
#define T_ 32
#define I_ 32
#define H_ 256
#define C_ 12

#define MT 128          // batch-tile rows per CTA
#define NTHREADS 512    // 16 warps: 2 (M) x 8 (N)
#define SB 264          // padded smem stride (halfs): 528B rows, ldmatrix-conflict-free
#define SWI 36          // padded stride for w_ih0 (32-wide rows)

// Inter-layer scratch (static device globals; no runtime allocation)
__device__ __align__(16) __half g_h1 [(size_t)B_ * T_ * H_];   // layer0 out, [b][t][h]
__device__ __align__(16) __half g_xw1[(size_t)B_ * T_ * H_];   // fragment-major per (t,bblock) tile

// ---------------------------------------------------------------------------
// primitives
// ---------------------------------------------------------------------------
__device__ __forceinline__ void mma16816(float c[4], const uint32_t a[4], const uint32_t b[2]) {
    asm volatile(
        "mma.sync.aligned.m16n8k16.row.col.f32.f16.f16.f32 "
        "{%0,%1,%2,%3}, {%4,%5,%6,%7}, {%8,%9}, {%0,%1,%2,%3};\n"
        : "+f"(c[0]), "+f"(c[1]), "+f"(c[2]), "+f"(c[3])
        : "r"(a[0]), "r"(a[1]), "r"(a[2]), "r"(a[3]), "r"(b[0]), "r"(b[1]));
}
__device__ __forceinline__ uint32_t ldb32(const __half* p) { return *(const uint32_t*)p; }
__device__ __forceinline__ float tanh_f32(float x) {
    float y; asm("tanh.approx.f32 %0, %1;" : "=f"(y) : "f"(x)); return y;
}
__device__ __forceinline__ uint32_t pack_h2(float a, float b) {
    __half2 h = __floats2half2_rn(a, b);
    return *reinterpret_cast<uint32_t*>(&h);
}
__device__ __forceinline__ uint32_t s2u(const void* p) {
    return (uint32_t)__cvta_generic_to_shared(p);
}
__device__ __forceinline__ void ldm4(uint32_t d[4], uint32_t addr) {
    asm volatile("ldmatrix.sync.aligned.m8n8.x4.shared.b16 {%0,%1,%2,%3}, [%4];"
        : "=r"(d[0]), "=r"(d[1]), "=r"(d[2]), "=r"(d[3]) : "r"(addr));
}

// ---------------------------------------------------------------------------
// scalar-LDS warp gemm (kept for the K=32 x-projection and FC side-mma)
// ---------------------------------------------------------------------------
template<int KTOT, int AST, int BST>
__device__ __forceinline__ void warp_gemm(const __half* __restrict__ As,
                                          const __half* __restrict__ Bs,
                                          float (&acc)[4][4][4],
                                          int wm, int wn, int lane)
{
    const int grp = lane >> 2, tig = lane & 3;
    #pragma unroll
    for (int k0 = 0; k0 < KTOT; k0 += 16) {
        uint32_t a[4][4];
        #pragma unroll
        for (int mi = 0; mi < 4; mi++) {
            const __half* ap = As + (wm * 64 + mi * 16 + grp) * AST + k0 + 2 * tig;
            a[mi][0] = ldb32(ap);
            a[mi][1] = ldb32(ap + 8 * AST);
            a[mi][2] = ldb32(ap + 8);
            a[mi][3] = ldb32(ap + 8 * AST + 8);
        }
        #pragma unroll
        for (int ni = 0; ni < 4; ni++) {
            const __half* bp = Bs + (wn * 32 + ni * 8 + grp) * BST + k0 + 2 * tig;
            uint32_t b[2];
            b[0] = ldb32(bp);
            b[1] = ldb32(bp + 8);
            #pragma unroll
            for (int mi = 0; mi < 4; mi++)
                mma16816(acc[mi][ni], a[mi], b);
        }
    }
}

// ---------------------------------------------------------------------------
// ldmatrix warp gemm for 256-wide operands (strides = SB)
// A regs {r0k0, r8k0, r0k8, r8k8}: rows r+(lane&8), col-bytes (lane&16)
// B regs {n0k0, n0k8, n8k0, n8k8}: rows r+((lane&16)>>1), col-bytes (lane&8)<<1
// ---------------------------------------------------------------------------
__device__ __forceinline__ void warp_gemm_ldm(uint32_t Abase, uint32_t Bbase,
                                              float (&acc)[4][4][4],
                                              int wm, int wn, int lane)
{
    const int r = lane & 7;
    const uint32_t aoff = (uint32_t)((r + (lane & 8)) * (SB * 2) + (lane & 16));
    const uint32_t boff = (uint32_t)((r + ((lane & 16) >> 1)) * (SB * 2) + ((lane & 8) << 1));
    const uint32_t aP = Abase + (uint32_t)(wm * 64 * (SB * 2)) + aoff;
    const uint32_t bP = Bbase + (uint32_t)(wn * 32 * (SB * 2)) + boff;

    #pragma unroll
    for (int k0 = 0; k0 < 256; k0 += 16) {
        uint32_t a[4][4];
        #pragma unroll
        for (int mi = 0; mi < 4; mi++)
            ldm4(a[mi], aP + (uint32_t)(mi * 16 * (SB * 2) + k0 * 2));
        #pragma unroll
        for (int nj = 0; nj < 4; nj += 2) {
            uint32_t b4[4];
            ldm4(b4, bP + (uint32_t)(nj * 8 * (SB * 2) + k0 * 2));
            uint32_t b0[2] = { b4[0], b4[1] };
            uint32_t b1[2] = { b4[2], b4[3] };
            #pragma unroll
            for (int mi = 0; mi < 4; mi++) {
                mma16816(acc[mi][nj],     a[mi], b0);
                mma16816(acc[mi][nj + 1], a[mi], b1);
            }
        }
    }
}

// ---------------------------------------------------------------------------
// Kernel 1: layer0 fused (input projection + recurrence), h1 -> g_h1 (fp16)
// ---------------------------------------------------------------------------
__global__ void __launch_bounds__(NTHREADS, 1)
layer0_kernel(const float* __restrict__ x, const float* __restrict__ w_ih,
              const float* __restrict__ w_hh, const float* __restrict__ b_ih,
              const float* __restrict__ b_hh)
{
    extern __shared__ char sm[];
    __half* Whhs = (__half*)sm;               // 256*SB
    __half* Hs   = Whhs + 256 * SB;           // MT*SB
    __half* Wihs = Hs + MT * SB;              // 256*SWI
    __half* Xs   = Wihs + 256 * SWI;          // MT*32
    float*  bs   = (float*)(Xs + MT * 32);    // 256

    const int tid = threadIdx.x;
    const int wid = tid >> 5, lane = tid & 31;
    const int wm = wid >> 3, wn = wid & 7;
    const int grp = lane >> 2, tig = lane & 3;
    const int b0 = blockIdx.x * MT;
    const uint32_t HsU = s2u(Hs), WhhU = s2u(Whhs);

    for (int e = tid; e < 256 * 256; e += NTHREADS) {
        int n = e >> 8, k = e & 255;
        Whhs[n * SB + k] = __float2half_rn(w_hh[e]);
    }
    for (int e = tid; e < 256 * 32; e += NTHREADS) {
        int n = e >> 5, k = e & 31;
        Wihs[n * SWI + k] = __float2half_rn(w_ih[e]);
    }
    if (tid < 256) bs[tid] = b_ih[tid] + b_hh[tid];
    for (int e = tid; e < MT * SB; e += NTHREADS) Hs[e] = __float2half_rn(0.f);

    // stage x_0 (each thread: 2 float4 of the 128x32 tile)
    const int r0i = tid >> 3, q0 = tid & 7;
    const int r1i = (tid + 512) >> 3, q1 = tid & 7;
    {
        float4 p0 = *(const float4*)(x + (size_t)(b0 + r0i) * (T_ * I_) + q0 * 4);
        float4 p1 = *(const float4*)(x + (size_t)(b0 + r1i) * (T_ * I_) + q1 * 4);
        *(uint2*)&Xs[r0i * 32 + q0 * 4] = make_uint2(pack_h2(p0.x, p0.y), pack_h2(p0.z, p0.w));
        *(uint2*)&Xs[r1i * 32 + q1 * 4] = make_uint2(pack_h2(p1.x, p1.y), pack_h2(p1.z, p1.w));
    }
    __syncthreads();

    for (int t = 0; t < T_; t++) {
        float4 p0, p1;
        if (t < T_ - 1) {
            p0 = *(const float4*)(x + (size_t)(b0 + r0i) * (T_ * I_) + (t + 1) * I_ + q0 * 4);
            p1 = *(const float4*)(x + (size_t)(b0 + r1i) * (T_ * I_) + (t + 1) * I_ + q1 * 4);
        }

        float acc[4][4][4];
        #pragma unroll
        for (int mi = 0; mi < 4; mi++)
            #pragma unroll
            for (int ni = 0; ni < 4; ni++)
                #pragma unroll
                for (int q = 0; q < 4; q++) acc[mi][ni][q] = 0.f;

        warp_gemm<32, 32, SWI>(Xs, Wihs, acc, wm, wn, lane);   // x_t @ Wih^T
        warp_gemm_ldm(HsU, WhhU, acc, wm, wn, lane);           // h_{t-1} @ Whh^T
        __syncthreads();

        if (t < T_ - 1) {
            *(uint2*)&Xs[r0i * 32 + q0 * 4] = make_uint2(pack_h2(p0.x, p0.y), pack_h2(p0.z, p0.w));
            *(uint2*)&Xs[r1i * 32 + q1 * 4] = make_uint2(pack_h2(p1.x, p1.y), pack_h2(p1.z, p1.w));
        }

        #pragma unroll
        for (int mi = 0; mi < 4; mi++) {
            int r0 = wm * 64 + mi * 16 + grp;
            #pragma unroll
            for (int ni = 0; ni < 4; ni++) {
                int c0 = wn * 32 + ni * 8 + 2 * tig;
                float bb0 = bs[c0], bb1 = bs[c0 + 1];
                uint32_t h01 = pack_h2(tanh_f32(acc[mi][ni][0] + bb0),
                                       tanh_f32(acc[mi][ni][1] + bb1));
                uint32_t h23 = pack_h2(tanh_f32(acc[mi][ni][2] + bb0),
                                       tanh_f32(acc[mi][ni][3] + bb1));
                *(uint32_t*)&Hs[r0 * SB + c0]       = h01;
                *(uint32_t*)&Hs[(r0 + 8) * SB + c0] = h23;
                size_t g0 = ((size_t)(b0 + r0) * T_ + t) * H_ + c0;
                size_t g1 = ((size_t)(b0 + r0 + 8) * T_ + t) * H_ + c0;
                *(uint32_t*)&g_h1[g0] = h01;
                *(uint32_t*)&g_h1[g1] = h23;
            }
        }
        __syncthreads();
    }
}

// ---------------------------------------------------------------------------
// Kernel 2: xw1 = h1 @ Wih1^T + bias. Tiles = (t, bblock); output FRAGMENT-MAJOR.
// NOTE: one (b,t) record of g_h1 = 256 halfs = 32 uint4 (the R4 bug was *16).
// ---------------------------------------------------------------------------
__global__ void __launch_bounds__(NTHREADS, 1)
proj1_kernel(const float* __restrict__ w_ih, const float* __restrict__ b_ih,
             const float* __restrict__ b_hh)
{
    extern __shared__ char sm[];
    __half* Ws = (__half*)sm;              // 256*SB
    __half* As = Ws + 256 * SB;            // MT*SB
    float*  bs = (float*)(As + MT * SB);   // 256

    const int tid = threadIdx.x;
    const int wid = tid >> 5, lane = tid & 31;
    const int wm = wid >> 3, wn = wid & 7;
    const int tig = lane & 3;
    const uint32_t AsU = s2u(As), WsU = s2u(Ws);

    for (int e = tid; e < 256 * 256; e += NTHREADS) {
        int n = e >> 8, k = e & 255;
        Ws[n * SB + k] = __float2half_rn(w_ih[e]);
    }
    if (tid < 256) bs[tid] = b_ih[tid] + b_hh[tid];

    for (int it = 0; it < 4; it++) {
        int tile = it * 1024 + blockIdx.x;     // tile = t*128 + bblock
        int t  = tile >> 7;
        int bb = tile & 127;

        // A rows: batch b = bb*128 + r at time t, from g_h1[b][t][:] (32 uint4/record)
        #pragma unroll
        for (int i = 0; i < 8; i++) {
            int c = tid + i * NTHREADS;        // 4096 uint4 chunks
            int r = c >> 5, cp = c & 31;
            const uint4* srcp = (const uint4*)g_h1 +
                ((size_t)(bb * 128 + r) * T_ + t) * 32 + cp;
            *(uint4*)&As[r * SB + cp * 8] = *srcp;
        }
        __syncthreads();                       // also covers Ws/bs on first iter

        float acc[4][4][4];
        #pragma unroll
        for (int mi = 0; mi < 4; mi++)
            #pragma unroll
            for (int ni = 0; ni < 4; ni++)
                #pragma unroll
                for (int q = 0; q < 4; q++) acc[mi][ni][q] = 0.f;

        warp_gemm_ldm(AsU, WsU, acc, wm, wn, lane);

        // fragment-major store: this thread's 64 halfs contiguous
        uint32_t v[32];
        #pragma unroll
        for (int mi = 0; mi < 4; mi++)
            #pragma unroll
            for (int ni = 0; ni < 4; ni++) {
                int c0 = wn * 32 + ni * 8 + 2 * tig;
                float bb0 = bs[c0], bb1 = bs[c0 + 1];
                v[mi * 8 + ni * 2 + 0] = pack_h2(acc[mi][ni][0] + bb0, acc[mi][ni][1] + bb1);
                v[mi * 8 + ni * 2 + 1] = pack_h2(acc[mi][ni][2] + bb0, acc[mi][ni][3] + bb1);
            }
        uint4* dst = (uint4*)g_xw1 + ((size_t)tile * NTHREADS + tid) * 8;
        const uint4* vv = (const uint4*)v;
        #pragma unroll
        for (int i = 0; i < 8; i++) dst[i] = vv[i];

        __syncthreads();
    }
}

// ---------------------------------------------------------------------------
// Kernel 3: layer1 recurrence + fused FC epilogue
// ---------------------------------------------------------------------------
__global__ void __launch_bounds__(NTHREADS, 1)
layer1_kernel(const float* __restrict__ w_hh, const float* __restrict__ fc_w,
              const float* __restrict__ fc_b, float* __restrict__ out)
{
    extern __shared__ char sm[];
    __half* Whhs = (__half*)sm;            // 256*SB
    __half* Hs   = Whhs + 256 * SB;        // MT*SB
    __half* Fs   = Hs + MT * SB;           // 16*SB (rows 12..15 stay zero)

    const int tid = threadIdx.x;
    const int wid = tid >> 5, lane = tid & 31;
    const int wm = wid >> 3, wn = wid & 7;
    const int grp = lane >> 2, tig = lane & 3;
    const int b0 = blockIdx.x * MT;
    const uint32_t HsU = s2u(Hs), WhhU = s2u(Whhs);

    for (int e = tid; e < 256 * 256; e += NTHREADS) {
        int n = e >> 8, k = e & 255;
        Whhs[n * SB + k] = __float2half_rn(w_hh[e]);
    }
    for (int e = tid; e < MT * SB; e += NTHREADS) Hs[e] = __float2half_rn(0.f);
    for (int e = tid; e < 16 * SB; e += NTHREADS) Fs[e] = __float2half_rn(0.f);
    __syncthreads();

    float accfc[4][4];
    #pragma unroll
    for (int mi = 0; mi < 4; mi++)
        #pragma unroll
        for (int q = 0; q < 4; q++) accfc[mi][q] = 0.f;

    for (int t = 0; t < T_; t++) {
        // acc init from fragment-major g_xw1: 8 contiguous LDG.128 per thread
        float acc[4][4][4];
        {
            const uint4* srcp = (const uint4*)g_xw1 +
                ((size_t)(t * 128 + blockIdx.x) * NTHREADS + tid) * 8;
            uint4 v[8];
            #pragma unroll
            for (int i = 0; i < 8; i++) v[i] = srcp[i];
            const uint32_t* vv = (const uint32_t*)v;
            #pragma unroll
            for (int mi = 0; mi < 4; mi++)
                #pragma unroll
                for (int ni = 0; ni < 4; ni++) {
                    float2 f0 = __half22float2(*(const __half2*)&vv[mi * 8 + ni * 2 + 0]);
                    float2 f1 = __half22float2(*(const __half2*)&vv[mi * 8 + ni * 2 + 1]);
                    acc[mi][ni][0] = f0.x; acc[mi][ni][1] = f0.y;
                    acc[mi][ni][2] = f1.x; acc[mi][ni][3] = f1.y;
                }
        }

        warp_gemm_ldm(HsU, WhhU, acc, wm, wn, lane);
        __syncthreads();   // Hs reads (gemm t) + Hs/Fs reads (FC of t-1) complete

        #pragma unroll
        for (int mi = 0; mi < 4; mi++) {
            int r0 = wm * 64 + mi * 16 + grp;
            #pragma unroll
            for (int ni = 0; ni < 4; ni++) {
                int c0 = wn * 32 + ni * 8 + 2 * tig;
                *(uint32_t*)&Hs[r0 * SB + c0] =
                    pack_h2(tanh_f32(acc[mi][ni][0]), tanh_f32(acc[mi][ni][1]));
                *(uint32_t*)&Hs[(r0 + 8) * SB + c0] =
                    pack_h2(tanh_f32(acc[mi][ni][2]), tanh_f32(acc[mi][ni][3]));
            }
        }
        #pragma unroll
        for (int i = 0; i < 6; i++) {
            int e = tid + i * NTHREADS;
            int c = e >> 8, j = e & 255;
            Fs[c * SB + j] = __float2half_rn(fc_w[(size_t)c * (T_ * H_) + t * H_ + j]);
        }
        __syncthreads();

        if (wid < 4) {
            int wm2 = wid >> 1, wn2 = wid & 1;
            #pragma unroll
            for (int k0 = 0; k0 < 256; k0 += 16) {
                const __half* bp = Fs + (wn2 * 8 + grp) * SB + k0 + 2 * tig;
                uint32_t b[2] = { ldb32(bp), ldb32(bp + 8) };
                #pragma unroll
                for (int mi = 0; mi < 4; mi++) {
                    const __half* ap = Hs + (wm2 * 64 + mi * 16 + grp) * SB + k0 + 2 * tig;
                    uint32_t a[4] = { ldb32(ap), ldb32(ap + 8 * SB),
                                      ldb32(ap + 8), ldb32(ap + 8 * SB + 8) };
                    mma16816(accfc[mi], a, b);
                }
            }
        }
    }

    if (wid < 4) {
        int wm2 = wid >> 1, wn2 = wid & 1;
        #pragma unroll
        for (int mi = 0; mi < 4; mi++) {
            int r = b0 + wm2 * 64 + mi * 16 + grp;
            int c0 = wn2 * 8 + 2 * tig;
            if (c0 < C_)     out[(size_t)r * C_ + c0]           = accfc[mi][0] + fc_b[c0];
            if (c0 + 1 < C_) out[(size_t)r * C_ + c0 + 1]       = accfc[mi][1] + fc_b[c0 + 1];
            if (c0 < C_)     out[(size_t)(r + 8) * C_ + c0]     = accfc[mi][2] + fc_b[c0];
            if (c0 + 1 < C_) out[(size_t)(r + 8) * C_ + c0 + 1] = accfc[mi][3] + fc_b[c0 + 1];
        }
    }
}

// ---------------------------------------------------------------------------
extern "C" void kernel_launch(void* const* d_in, const int* in_sizes, int n_in,
                              void* d_out, int out_size)
{
    const float* x     = (const float*)d_in[0];
    const float* w_ih0 = (const float*)d_in[1];
    const float* w_hh0 = (const float*)d_in[2];
    const float* b_ih0 = (const float*)d_in[3];
    const float* b_hh0 = (const float*)d_in[4];
    const float* w_ih1 = (const float*)d_in[5];
    const float* w_hh1 = (const float*)d_in[6];
    const float* b_ih1 = (const float*)d_in[7];
    const float* b_hh1 = (const float*)d_in[8];
    const float* fc_w  = (const float*)d_in[9];
    const float* fc_b  = (const float*)d_in[10];
    float* out = (float*)d_out;

    const int smem0 = (256 * SB + MT * SB + 256 * SWI + MT * 32) * 2 + 256 * 4; // 230400
    const int smem2 = (256 * SB + MT * SB) * 2 + 256 * 4;                       // 203776
    const int smem1 = (256 * SB + MT * SB + 16 * SB) * 2;                       // 211200

    cudaFuncSetAttribute(layer0_kernel, cudaFuncAttributeMaxDynamicSharedMemorySize, smem0);
    cudaFuncSetAttribute(proj1_kernel,  cudaFuncAttributeMaxDynamicSharedMemorySize, smem2);
    cudaFuncSetAttribute(layer1_kernel, cudaFuncAttributeMaxDynamicSharedMemorySize, smem1);

    layer0_kernel<<<B_ / MT, NTHREADS, smem0>>>(x, w_ih0, w_hh0, b_ih0, b_hh0);
    proj1_kernel<<<1024, NTHREADS, smem2>>>(w_ih1, b_ih1, b_hh1);
    layer1_kernel<<<B_ / MT, NTHREADS, smem1>>>(w_hh1, fc_w, fc_b, out);
}

// round 10
// speedup vs baseline: 1.0116x; 1.0116x over previous
#include <cuda_runtime.h>
#include <cuda_fp16.h>
#include <stdint.h>

// Problem constants
#define B_ 16384
#define T_ 32
#define I_ 32
#define H_ 256
#define C_ 12

#define MT 128          // batch-tile rows per CTA
#define NTHREADS 512    // 16 warps: 2 (M) x 8 (N)
#define SB 264          // padded smem stride (halfs): 528B rows, ldmatrix-conflict-free
#define SWI 36          // padded stride for w_ih0 (32-wide rows)

// Inter-layer scratch (static device globals; no runtime allocation)
__device__ __align__(16) __half g_h1 [(size_t)B_ * T_ * H_];   // layer0 out, [b][t][h]
__device__ __align__(16) __half g_xw1[(size_t)B_ * T_ * H_];   // fragment-major per (t,bblock) tile

// ---------------------------------------------------------------------------
// primitives
// ---------------------------------------------------------------------------
__device__ __forceinline__ void mma16816(float c[4], const uint32_t a[4], const uint32_t b[2]) {
    asm volatile(
        "mma.sync.aligned.m16n8k16.row.col.f32.f16.f16.f32 "
        "{%0,%1,%2,%3}, {%4,%5,%6,%7}, {%8,%9}, {%0,%1,%2,%3};\n"
        : "+f"(c[0]), "+f"(c[1]), "+f"(c[2]), "+f"(c[3])
        : "r"(a[0]), "r"(a[1]), "r"(a[2]), "r"(a[3]), "r"(b[0]), "r"(b[1]));
}
__device__ __forceinline__ uint32_t ldb32(const __half* p) { return *(const uint32_t*)p; }
__device__ __forceinline__ float tanh_f32(float x) {
    float y; asm("tanh.approx.f32 %0, %1;" : "=f"(y) : "f"(x)); return y;
}
__device__ __forceinline__ uint32_t pack_h2(float a, float b) {
    __half2 h = __floats2half2_rn(a, b);
    return *reinterpret_cast<uint32_t*>(&h);
}
__device__ __forceinline__ uint32_t s2u(const void* p) {
    return (uint32_t)__cvta_generic_to_shared(p);
}
__device__ __forceinline__ void ldm4(uint32_t d[4], uint32_t addr) {
    asm volatile("ldmatrix.sync.aligned.m8n8.x4.shared.b16 {%0,%1,%2,%3}, [%4];"
        : "=r"(d[0]), "=r"(d[1]), "=r"(d[2]), "=r"(d[3]) : "r"(addr));
}

// ---------------------------------------------------------------------------
// scalar-LDS warp gemm (K=32 x-projection and FC side-mma)
// ---------------------------------------------------------------------------
template<int KTOT, int AST, int BST>
__device__ __forceinline__ void warp_gemm(const __half* __restrict__ As,
                                          const __half* __restrict__ Bs,
                                          float (&acc)[4][4][4],
                                          int wm, int wn, int lane)
{
    const int grp = lane >> 2, tig = lane & 3;
    #pragma unroll
    for (int k0 = 0; k0 < KTOT; k0 += 16) {
        uint32_t a[4][4];
        #pragma unroll
        for (int mi = 0; mi < 4; mi++) {
            const __half* ap = As + (wm * 64 + mi * 16 + grp) * AST + k0 + 2 * tig;
            a[mi][0] = ldb32(ap);
            a[mi][1] = ldb32(ap + 8 * AST);
            a[mi][2] = ldb32(ap + 8);
            a[mi][3] = ldb32(ap + 8 * AST + 8);
        }
        #pragma unroll
        for (int ni = 0; ni < 4; ni++) {
            const __half* bp = Bs + (wn * 32 + ni * 8 + grp) * BST + k0 + 2 * tig;
            uint32_t b[2];
            b[0] = ldb32(bp);
            b[1] = ldb32(bp + 8);
            #pragma unroll
            for (int mi = 0; mi < 4; mi++)
                mma16816(acc[mi][ni], a[mi], b);
        }
    }
}

// ---------------------------------------------------------------------------
// ldmatrix warp gemm for 256-wide operands (strides = SB)
// ---------------------------------------------------------------------------
__device__ __forceinline__ void warp_gemm_ldm(uint32_t Abase, uint32_t Bbase,
                                              float (&acc)[4][4][4],
                                              int wm, int wn, int lane)
{
    const int r = lane & 7;
    const uint32_t aoff = (uint32_t)((r + (lane & 8)) * (SB * 2) + (lane & 16));
    const uint32_t boff = (uint32_t)((r + ((lane & 16) >> 1)) * (SB * 2) + ((lane & 8) << 1));
    const uint32_t aP = Abase + (uint32_t)(wm * 64 * (SB * 2)) + aoff;
    const uint32_t bP = Bbase + (uint32_t)(wn * 32 * (SB * 2)) + boff;

    #pragma unroll
    for (int k0 = 0; k0 < 256; k0 += 16) {
        uint32_t a[4][4];
        #pragma unroll
        for (int mi = 0; mi < 4; mi++)
            ldm4(a[mi], aP + (uint32_t)(mi * 16 * (SB * 2) + k0 * 2));
        #pragma unroll
        for (int nj = 0; nj < 4; nj += 2) {
            uint32_t b4[4];
            ldm4(b4, bP + (uint32_t)(nj * 8 * (SB * 2) + k0 * 2));
            uint32_t b0[2] = { b4[0], b4[1] };
            uint32_t b1[2] = { b4[2], b4[3] };
            #pragma unroll
            for (int mi = 0; mi < 4; mi++) {
                mma16816(acc[mi][nj],     a[mi], b0);
                mma16816(acc[mi][nj + 1], a[mi], b1);
            }
        }
    }
}

// ---------------------------------------------------------------------------
// Kernel 1: layer0. Critical-path split: tanh/pack/STG before bar1 (overlaps
// straggler gemms); only the Hs/Xs smem stores sit between the two barriers.
// ---------------------------------------------------------------------------
__global__ void __launch_bounds__(NTHREADS, 1)
layer0_kernel(const float* __restrict__ x, const float* __restrict__ w_ih,
              const float* __restrict__ w_hh, const float* __restrict__ b_ih,
              const float* __restrict__ b_hh)
{
    extern __shared__ char sm[];
    __half* Whhs = (__half*)sm;               // 256*SB
    __half* Hs   = Whhs + 256 * SB;           // MT*SB
    __half* Wihs = Hs + MT * SB;              // 256*SWI
    __half* Xs   = Wihs + 256 * SWI;          // MT*32
    float*  bs   = (float*)(Xs + MT * 32);    // 256

    const int tid = threadIdx.x;
    const int wid = tid >> 5, lane = tid & 31;
    const int wm = wid >> 3, wn = wid & 7;
    const int grp = lane >> 2, tig = lane & 3;
    const int b0 = blockIdx.x * MT;
    const uint32_t HsU = s2u(Hs), WhhU = s2u(Whhs);

    for (int e = tid; e < 256 * 256; e += NTHREADS) {
        int n = e >> 8, k = e & 255;
        Whhs[n * SB + k] = __float2half_rn(w_hh[e]);
    }
    for (int e = tid; e < 256 * 32; e += NTHREADS) {
        int n = e >> 5, k = e & 31;
        Wihs[n * SWI + k] = __float2half_rn(w_ih[e]);
    }
    if (tid < 256) bs[tid] = b_ih[tid] + b_hh[tid];
    for (int e = tid; e < MT * SB; e += NTHREADS) Hs[e] = __float2half_rn(0.f);

    // stage x_0 (each thread: 2 float4 of the 128x32 tile)
    const int r0i = tid >> 3, q0 = tid & 7;
    const int r1i = (tid + 512) >> 3, q1 = tid & 7;
    {
        float4 p0 = *(const float4*)(x + (size_t)(b0 + r0i) * (T_ * I_) + q0 * 4);
        float4 p1 = *(const float4*)(x + (size_t)(b0 + r1i) * (T_ * I_) + q1 * 4);
        *(uint2*)&Xs[r0i * 32 + q0 * 4] = make_uint2(pack_h2(p0.x, p0.y), pack_h2(p0.z, p0.w));
        *(uint2*)&Xs[r1i * 32 + q1 * 4] = make_uint2(pack_h2(p1.x, p1.y), pack_h2(p1.z, p1.w));
    }
    __syncthreads();

    for (int t = 0; t < T_; t++) {
        float4 p0, p1;
        if (t < T_ - 1) {
            p0 = *(const float4*)(x + (size_t)(b0 + r0i) * (T_ * I_) + (t + 1) * I_ + q0 * 4);
            p1 = *(const float4*)(x + (size_t)(b0 + r1i) * (T_ * I_) + (t + 1) * I_ + q1 * 4);
        }

        float acc[4][4][4];
        #pragma unroll
        for (int mi = 0; mi < 4; mi++)
            #pragma unroll
            for (int ni = 0; ni < 4; ni++)
                #pragma unroll
                for (int q = 0; q < 4; q++) acc[mi][ni][q] = 0.f;

        warp_gemm<32, 32, SWI>(Xs, Wihs, acc, wm, wn, lane);   // x_t @ Wih^T
        warp_gemm_ldm(HsU, WhhU, acc, wm, wn, lane);           // h_{t-1} @ Whh^T

        // tanh + pack + global store BEFORE the barrier (no smem writes here)
        uint32_t pk01[16], pk23[16];
        #pragma unroll
        for (int mi = 0; mi < 4; mi++) {
            int r0 = wm * 64 + mi * 16 + grp;
            #pragma unroll
            for (int ni = 0; ni < 4; ni++) {
                int c0 = wn * 32 + ni * 8 + 2 * tig;
                float bb0 = bs[c0], bb1 = bs[c0 + 1];
                int idx = mi * 4 + ni;
                pk01[idx] = pack_h2(tanh_f32(acc[mi][ni][0] + bb0),
                                    tanh_f32(acc[mi][ni][1] + bb1));
                pk23[idx] = pack_h2(tanh_f32(acc[mi][ni][2] + bb0),
                                    tanh_f32(acc[mi][ni][3] + bb1));
                size_t g0 = ((size_t)(b0 + r0) * T_ + t) * H_ + c0;
                size_t g1 = ((size_t)(b0 + r0 + 8) * T_ + t) * H_ + c0;
                *(uint32_t*)&g_h1[g0] = pk01[idx];
                *(uint32_t*)&g_h1[g1] = pk23[idx];
            }
        }
        __syncthreads();   // bar1: all gemm smem reads complete

        // ONLY smem stores between the barriers
        #pragma unroll
        for (int mi = 0; mi < 4; mi++) {
            int r0 = wm * 64 + mi * 16 + grp;
            #pragma unroll
            for (int ni = 0; ni < 4; ni++) {
                int c0 = wn * 32 + ni * 8 + 2 * tig;
                *(uint32_t*)&Hs[r0 * SB + c0]       = pk01[mi * 4 + ni];
                *(uint32_t*)&Hs[(r0 + 8) * SB + c0] = pk23[mi * 4 + ni];
            }
        }
        if (t < T_ - 1) {
            *(uint2*)&Xs[r0i * 32 + q0 * 4] = make_uint2(pack_h2(p0.x, p0.y), pack_h2(p0.z, p0.w));
            *(uint2*)&Xs[r1i * 32 + q1 * 4] = make_uint2(pack_h2(p1.x, p1.y), pack_h2(p1.z, p1.w));
        }
        __syncthreads();   // bar2: h_t / x_{t+1} visible
    }
}

// ---------------------------------------------------------------------------
// Kernel 2: xw1 = h1 @ Wih1^T + bias. Tiles = (t, bblock); output FRAGMENT-MAJOR.
// ---------------------------------------------------------------------------
__global__ void __launch_bounds__(NTHREADS, 1)
proj1_kernel(const float* __restrict__ w_ih, const float* __restrict__ b_ih,
             const float* __restrict__ b_hh)
{
    extern __shared__ char sm[];
    __half* Ws = (__half*)sm;              // 256*SB
    __half* As = Ws + 256 * SB;            // MT*SB
    float*  bs = (float*)(As + MT * SB);   // 256

    const int tid = threadIdx.x;
    const int wid = tid >> 5, lane = tid & 31;
    const int wm = wid >> 3, wn = wid & 7;
    const int tig = lane & 3;
    const uint32_t AsU = s2u(As), WsU = s2u(Ws);

    for (int e = tid; e < 256 * 256; e += NTHREADS) {
        int n = e >> 8, k = e & 255;
        Ws[n * SB + k] = __float2half_rn(w_ih[e]);
    }
    if (tid < 256) bs[tid] = b_ih[tid] + b_hh[tid];

    for (int it = 0; it < 4; it++) {
        int tile = it * 1024 + blockIdx.x;     // tile = t*128 + bblock
        int t  = tile >> 7;
        int bb = tile & 127;

        // A rows: batch b = bb*128 + r at time t, g_h1[b][t][:] = 32 uint4/record
        #pragma unroll
        for (int i = 0; i < 8; i++) {
            int c = tid + i * NTHREADS;
            int r = c >> 5, cp = c & 31;
            const uint4* srcp = (const uint4*)g_h1 +
                ((size_t)(bb * 128 + r) * T_ + t) * 32 + cp;
            *(uint4*)&As[r * SB + cp * 8] = *srcp;
        }
        __syncthreads();

        float acc[4][4][4];
        #pragma unroll
        for (int mi = 0; mi < 4; mi++)
            #pragma unroll
            for (int ni = 0; ni < 4; ni++)
                #pragma unroll
                for (int q = 0; q < 4; q++) acc[mi][ni][q] = 0.f;

        warp_gemm_ldm(AsU, WsU, acc, wm, wn, lane);

        uint32_t v[32];
        #pragma unroll
        for (int mi = 0; mi < 4; mi++)
            #pragma unroll
            for (int ni = 0; ni < 4; ni++) {
                int c0 = wn * 32 + ni * 8 + 2 * tig;
                float bb0 = bs[c0], bb1 = bs[c0 + 1];
                v[mi * 8 + ni * 2 + 0] = pack_h2(acc[mi][ni][0] + bb0, acc[mi][ni][1] + bb1);
                v[mi * 8 + ni * 2 + 1] = pack_h2(acc[mi][ni][2] + bb0, acc[mi][ni][3] + bb1);
            }
        uint4* dst = (uint4*)g_xw1 + ((size_t)tile * NTHREADS + tid) * 8;
        const uint4* vv = (const uint4*)v;
        #pragma unroll
        for (int i = 0; i < 8; i++) dst[i] = vv[i];

        __syncthreads();
    }
}

// ---------------------------------------------------------------------------
// Kernel 3: layer1 recurrence + fused FC. Same critical-path split as layer0:
// fc_w LDG + tanh/pack before barA; only STS between barA and barB.
// ---------------------------------------------------------------------------
__global__ void __launch_bounds__(NTHREADS, 1)
layer1_kernel(const float* __restrict__ w_hh, const float* __restrict__ fc_w,
              const float* __restrict__ fc_b, float* __restrict__ out)
{
    extern __shared__ char sm[];
    __half* Whhs = (__half*)sm;            // 256*SB
    __half* Hs   = Whhs + 256 * SB;        // MT*SB
    __half* Fs   = Hs + MT * SB;           // 16*SB (rows 12..15 stay zero)

    const int tid = threadIdx.x;
    const int wid = tid >> 5, lane = tid & 31;
    const int wm = wid >> 3, wn = wid & 7;
    const int grp = lane >> 2, tig = lane & 3;
    const int b0 = blockIdx.x * MT;
    const uint32_t HsU = s2u(Hs), WhhU = s2u(Whhs);

    for (int e = tid; e < 256 * 256; e += NTHREADS) {
        int n = e >> 8, k = e & 255;
        Whhs[n * SB + k] = __float2half_rn(w_hh[e]);
    }
    for (int e = tid; e < MT * SB; e += NTHREADS) Hs[e] = __float2half_rn(0.f);
    for (int e = tid; e < 16 * SB; e += NTHREADS) Fs[e] = __float2half_rn(0.f);
    __syncthreads();

    float accfc[4][4];
    #pragma unroll
    for (int mi = 0; mi < 4; mi++)
        #pragma unroll
        for (int q = 0; q < 4; q++) accfc[mi][q] = 0.f;

    for (int t = 0; t < T_; t++) {
        // acc init from fragment-major g_xw1: 8 contiguous LDG.128 per thread
        float acc[4][4][4];
        {
            const uint4* srcp = (const uint4*)g_xw1 +
                ((size_t)(t * 128 + blockIdx.x) * NTHREADS + tid) * 8;
            uint4 v[8];
            #pragma unroll
            for (int i = 0; i < 8; i++) v[i] = srcp[i];
            const uint32_t* vv = (const uint32_t*)v;
            #pragma unroll
            for (int mi = 0; mi < 4; mi++)
                #pragma unroll
                for (int ni = 0; ni < 4; ni++) {
                    float2 f0 = __half22float2(*(const __half2*)&vv[mi * 8 + ni * 2 + 0]);
                    float2 f1 = __half22float2(*(const __half2*)&vv[mi * 8 + ni * 2 + 1]);
                    acc[mi][ni][0] = f0.x; acc[mi][ni][1] = f0.y;
                    acc[mi][ni][2] = f1.x; acc[mi][ni][3] = f1.y;
                }
        }

        warp_gemm_ldm(HsU, WhhU, acc, wm, wn, lane);

        // fc_w prefetch (global) + tanh/pack — all before barA
        float fcv[6];
        #pragma unroll
        for (int i = 0; i < 6; i++) {
            int e = tid + i * NTHREADS;
            fcv[i] = fc_w[(size_t)(e >> 8) * (T_ * H_) + t * H_ + (e & 255)];
        }
        uint32_t pk01[16], pk23[16];
        #pragma unroll
        for (int mi = 0; mi < 4; mi++) {
            #pragma unroll
            for (int ni = 0; ni < 4; ni++) {
                int idx = mi * 4 + ni;
                pk01[idx] = pack_h2(tanh_f32(acc[mi][ni][0]), tanh_f32(acc[mi][ni][1]));
                pk23[idx] = pack_h2(tanh_f32(acc[mi][ni][2]), tanh_f32(acc[mi][ni][3]));
            }
        }
        __syncthreads();   // barA: gemm(t) + FC(t-1) smem reads complete

        // ONLY smem stores between barriers
        #pragma unroll
        for (int mi = 0; mi < 4; mi++) {
            int r0 = wm * 64 + mi * 16 + grp;
            #pragma unroll
            for (int ni = 0; ni < 4; ni++) {
                int c0 = wn * 32 + ni * 8 + 2 * tig;
                *(uint32_t*)&Hs[r0 * SB + c0]       = pk01[mi * 4 + ni];
                *(uint32_t*)&Hs[(r0 + 8) * SB + c0] = pk23[mi * 4 + ni];
            }
        }
        #pragma unroll
        for (int i = 0; i < 6; i++) {
            int e = tid + i * NTHREADS;
            Fs[(e >> 8) * SB + (e & 255)] = __float2half_rn(fcv[i]);
        }
        __syncthreads();   // barB: h_t and fc slice ready

        // FC side-mma: warps 0..3 (overlaps next-step gemm of warps 4..15)
        if (wid < 4) {
            int wm2 = wid >> 1, wn2 = wid & 1;
            #pragma unroll
            for (int k0 = 0; k0 < 256; k0 += 16) {
                const __half* bp = Fs + (wn2 * 8 + grp) * SB + k0 + 2 * tig;
                uint32_t b[2] = { ldb32(bp), ldb32(bp + 8) };
                #pragma unroll
                for (int mi = 0; mi < 4; mi++) {
                    const __half* ap = Hs + (wm2 * 64 + mi * 16 + grp) * SB + k0 + 2 * tig;
                    uint32_t a[4] = { ldb32(ap), ldb32(ap + 8 * SB),
                                      ldb32(ap + 8), ldb32(ap + 8 * SB + 8) };
                    mma16816(accfc[mi], a, b);
                }
            }
        }
    }

    if (wid < 4) {
        int wm2 = wid >> 1, wn2 = wid & 1;
        #pragma unroll
        for (int mi = 0; mi < 4; mi++) {
            int r = b0 + wm2 * 64 + mi * 16 + grp;
            int c0 = wn2 * 8 + 2 * tig;
            if (c0 < C_)     out[(size_t)r * C_ + c0]           = accfc[mi][0] + fc_b[c0];
            if (c0 + 1 < C_) out[(size_t)r * C_ + c0 + 1]       = accfc[mi][1] + fc_b[c0 + 1];
            if (c0 < C_)     out[(size_t)(r + 8) * C_ + c0]     = accfc[mi][2] + fc_b[c0];
            if (c0 + 1 < C_) out[(size_t)(r + 8) * C_ + c0 + 1] = accfc[mi][3] + fc_b[c0 + 1];
        }
    }
}

// No-op 4th launch: shifts ncu's "-s 5 -c 1" capture window so a different
// kernel (expected: proj1) gets profiled. Negligible runtime cost.
__global__ void probe_kernel() {}

// ---------------------------------------------------------------------------
extern "C" void kernel_launch(void* const* d_in, const int* in_sizes, int n_in,
                              void* d_out, int out_size)
{
    const float* x     = (const float*)d_in[0];
    const float* w_ih0 = (const float*)d_in[1];
    const float* w_hh0 = (const float*)d_in[2];
    const float* b_ih0 = (const float*)d_in[3];
    const float* b_hh0 = (const float*)d_in[4];
    const float* w_ih1 = (const float*)d_in[5];
    const float* w_hh1 = (const float*)d_in[6];
    const float* b_ih1 = (const float*)d_in[7];
    const float* b_hh1 = (const float*)d_in[8];
    const float* fc_w  = (const float*)d_in[9];
    const float* fc_b  = (const float*)d_in[10];
    float* out = (float*)d_out;

    const int smem0 = (256 * SB + MT * SB + 256 * SWI + MT * 32) * 2 + 256 * 4; // 230400
    const int smem2 = (256 * SB + MT * SB) * 2 + 256 * 4;                       // 203776
    const int smem1 = (256 * SB + MT * SB + 16 * SB) * 2;                       // 211200

    cudaFuncSetAttribute(layer0_kernel, cudaFuncAttributeMaxDynamicSharedMemorySize, smem0);
    cudaFuncSetAttribute(proj1_kernel,  cudaFuncAttributeMaxDynamicSharedMemorySize, smem2);
    cudaFuncSetAttribute(layer1_kernel, cudaFuncAttributeMaxDynamicSharedMemorySize, smem1);

    layer0_kernel<<<B_ / MT, NTHREADS, smem0>>>(x, w_ih0, w_hh0, b_ih0, b_hh0);
    proj1_kernel<<<1024, NTHREADS, smem2>>>(w_ih1, b_ih1, b_hh1);
    layer1_kernel<<<B_ / MT, NTHREADS, smem1>>>(w_hh1, fc_w, fc_b, out);
    probe_kernel<<<1, 1>>>();
}